// round 8
// baseline (speedup 1.0000x reference)
#include <cuda_runtime.h>
#include <cuda_bf16.h>
#include <cstdint>

#define Bc 8
#define Gc 256
#define Nn 1024
#define Pc 4
#define Fc 256
#define Kc 4
#define NBP 32
#define MAXS 128

// ======================= device scratch ======================================
__device__ float g_e1[NBP * Nn];
__device__ float g_e2[NBP * Nn];
__device__ float g_m[NBP * Nn];
__device__ float g_s[NBP * Nn];
__device__ int g_cnt[Bc * Nn];
__device__ unsigned short g_idx[(size_t)Bc * Nn * MAXS];    // 2 MB
__device__ float g_av[(size_t)NBP * Nn * MAXS];             // 16 MB
__device__ float g_zf[(size_t)NBP * Nn * Nn];               // 128 MB zT fp32 [bp][n][kG]
__device__ __nv_bfloat16 g_zh[(size_t)NBP * Nn * Nn];       // 64 MB zT hi
__device__ __nv_bfloat16 g_zl[(size_t)NBP * Nn * Nn];       // 64 MB zT lo
__device__ __nv_bfloat16 g_fwh[(size_t)Pc * Fc * Kc * Gc];
__device__ __nv_bfloat16 g_fwl[(size_t)Pc * Fc * Kc * Gc];

__device__ __forceinline__ void split2(float v, __nv_bfloat16& h, __nv_bfloat16& l) {
    h = __float2bfloat16(v);
    l = __float2bfloat16(v - __bfloat162float(h));
}

// ======================= helpers =============================================
__device__ __forceinline__ uint32_t smem_u32(const void* p) {
    uint32_t a;
    asm("{ .reg .u64 t; cvta.to.shared.u64 t, %1; cvt.u32.u64 %0, t; }" : "=r"(a) : "l"(p));
    return a;
}
__device__ __forceinline__ void cpa16(uint32_t dst, const void* src) {
    asm volatile("cp.async.cg.shared.global [%0], [%1], 16;" :: "r"(dst), "l"(src));
}
__device__ __forceinline__ void cpa_commit() { asm volatile("cp.async.commit_group;" ::: "memory"); }
__device__ __forceinline__ void cpa_wait2() { asm volatile("cp.async.wait_group 2;" ::: "memory"); }
__device__ __forceinline__ void cpa_wait1() { asm volatile("cp.async.wait_group 1;" ::: "memory"); }
__device__ __forceinline__ void cpa_wait0() { asm volatile("cp.async.wait_group 0;" ::: "memory"); }

#define SWZ(off) ((off) ^ (((off) >> 3) & 0x70))

__device__ __forceinline__ void ldm_x4(uint32_t& r0, uint32_t& r1, uint32_t& r2, uint32_t& r3,
                                       uint32_t addr) {
    asm volatile("ldmatrix.sync.aligned.m8n8.x4.shared.b16 {%0,%1,%2,%3}, [%4];"
                 : "=r"(r0), "=r"(r1), "=r"(r2), "=r"(r3) : "r"(addr));
}
__device__ __forceinline__ void ldm_x2(uint32_t& r0, uint32_t& r1, uint32_t addr) {
    asm volatile("ldmatrix.sync.aligned.m8n8.x2.shared.b16 {%0,%1}, [%2];"
                 : "=r"(r0), "=r"(r1) : "r"(addr));
}
__device__ __forceinline__ void mma16816(float* c, const uint32_t* a, const uint32_t* b) {
    asm volatile(
        "mma.sync.aligned.m16n8k16.row.col.f32.bf16.bf16.f32 "
        "{%0,%1,%2,%3}, {%4,%5,%6,%7}, {%8,%9}, {%0,%1,%2,%3};"
        : "+f"(c[0]), "+f"(c[1]), "+f"(c[2]), "+f"(c[3])
        : "r"(a[0]), "r"(a[1]), "r"(a[2]), "r"(a[3]), "r"(b[0]), "r"(b[1]));
}

// ======================= 1. split: x -> zT slice0 (fp32 + hi/lo), fw -> hi/lo =
__global__ void split_kernel(const float* __restrict__ x, const float* __restrict__ fw) {
    int b = blockIdx.z;
    int g0 = blockIdx.y * 32, n0 = blockIdx.x * 32;
    __shared__ float t[32][33];
    int tx = threadIdx.x, ty = threadIdx.y;
    const float* xp = x + ((size_t)b * Gc + g0) * Nn + n0;
#pragma unroll
    for (int q = 0; q < 4; ++q) {
        int g = ty + q * 8;
        t[g][tx] = xp[(size_t)g * Nn + tx];
    }
    __syncthreads();
#pragma unroll
    for (int q = 0; q < 4; ++q) {
        int nn = ty + q * 8;
        float v = t[tx][nn];  // = x[b][g0+tx][n0+nn]
        __nv_bfloat16 h, l;
        split2(v, h, l);
#pragma unroll
        for (int p = 0; p < 4; ++p) {
            size_t o = (((size_t)(b * 4 + p) * Nn) + n0 + nn) * Nn + g0 + tx;  // slice0: col = g
            g_zf[o] = v;
            g_zh[o] = h;
            g_zl[o] = l;
        }
    }
    // fw split (grid-strided over all blocks)
    const int FT = Pc * Fc * Kc * Gc;
    int tot = gridDim.x * gridDim.y * gridDim.z * 256;
    int gid = ((blockIdx.z * gridDim.y + blockIdx.y) * gridDim.x + blockIdx.x) * 256 + ty * 32 + tx;
    for (int i = gid; i < FT; i += tot) {
        __nv_bfloat16 h, l;
        split2(fw[i], h, l);
        g_fwh[i] = h;
        g_fwl[i] = l;
    }
}

// ======================= 2. pe: e1/e2[bp][n] ===================================
__global__ void pe_kernel(const float* __restrict__ x,
                          const float* __restrict__ mixer,
                          const float* __restrict__ weight,
                          const float* __restrict__ wb) {
    int bp = blockIdx.y;
    int b = bp >> 2, p = bp & 3;
    int tid = threadIdx.x;
    __shared__ float s1[Gc], s2[Gc], sc[2];
    {
        int g = tid;
        float v1 = 0.f, v2 = 0.f;
        const float* mw1 = mixer + p * 2 * Fc;
        const float* mw2 = mw1 + Fc;
#pragma unroll 8
        for (int f = 0; f < Fc; ++f) {
            float w = weight[((size_t)(p * Fc + f)) * Gc + g];
            v1 = fmaf(mw1[f], w, v1);
            v2 = fmaf(mw2[f], w, v2);
        }
        s1[g] = v1;
        s2[g] = v2;
        if (g == 0) {
            float c1 = 0.f, c2 = 0.f;
            for (int f = 0; f < Fc; ++f) {
                c1 = fmaf(mw1[f], wb[p * Fc + f], c1);
                c2 = fmaf(mw2[f], wb[p * Fc + f], c2);
            }
            sc[0] = c1;
            sc[1] = c2;
        }
    }
    __syncthreads();
    int n = blockIdx.x * blockDim.x + tid;
    const float* xb = x + (size_t)b * Gc * Nn + n;
    float a1 = 0.f, a2 = 0.f;
#pragma unroll 8
    for (int g = 0; g < Gc; ++g) {
        float xv = xb[(size_t)g * Nn];
        a1 = fmaf(s1[g], xv, a1);
        a2 = fmaf(s2[g], xv, a2);
    }
    g_e1[bp * Nn + n] = a1 + sc[0];
    g_e2[bp * Nn + n] = a2 + sc[1];
}

// ======================= 3. idx: CSC pattern of S[b] ===========================
__global__ void idx_kernel(const float* __restrict__ S) {
    int b = blockIdx.y;
    int j = blockIdx.x * 256 + threadIdx.x;
    const float* Sb = S + (size_t)b * Nn * Nn + j;
    unsigned short* ip = g_idx + ((size_t)b * Nn + j) * MAXS;
    int c = 0;
#pragma unroll 4
    for (int i = 0; i < Nn; ++i) {
        float s = Sb[(size_t)i * Nn];
        if (fabsf(s) > 1e-9f) {
            if (c < MAXS) ip[c] = (unsigned short)i;
            ++c;
        }
    }
    g_cnt[b * Nn + j] = c < MAXS ? c : MAXS;
}

// ======================= reductions ==========================================
__device__ __forceinline__ float blockReduceMax(float v, float* sm) {
#pragma unroll
    for (int o = 16; o; o >>= 1) v = fmaxf(v, __shfl_xor_sync(0xffffffffu, v, o));
    if ((threadIdx.x & 31) == 0) sm[threadIdx.x >> 5] = v;
    __syncthreads();
    if (threadIdx.x < 32) {
        float t = (threadIdx.x < 8) ? sm[threadIdx.x] : -3.0e38f;
#pragma unroll
        for (int o = 4; o; o >>= 1) t = fmaxf(t, __shfl_xor_sync(0xffffffffu, t, o));
        if (threadIdx.x == 0) sm[0] = t;
    }
    __syncthreads();
    float r = sm[0];
    __syncthreads();
    return r;
}
__device__ __forceinline__ float blockReduceSum(float v, float* sm) {
#pragma unroll
    for (int o = 16; o; o >>= 1) v += __shfl_xor_sync(0xffffffffu, v, o);
    if ((threadIdx.x & 31) == 0) sm[threadIdx.x >> 5] = v;
    __syncthreads();
    if (threadIdx.x < 32) {
        float t = (threadIdx.x < 8) ? sm[threadIdx.x] : 0.f;
#pragma unroll
        for (int o = 4; o; o >>= 1) t += __shfl_xor_sync(0xffffffffu, t, o);
        if (threadIdx.x == 0) sm[0] = t;
    }
    __syncthreads();
    float r = sm[0];
    __syncthreads();
    return r;
}

// ======================= 4. ms: per-row softmax stats ==========================
__global__ void ms_kernel(const float* __restrict__ S) {
    int i = blockIdx.x, bp = blockIdx.y, b = bp >> 2;
    __shared__ float sm[8];
    float e2i = g_e2[bp * Nn + i];
    const float* e1r = g_e1 + bp * Nn;
    const float* Sr = S + (size_t)b * Nn * Nn + (size_t)i * Nn;
    float lv[4];
    int mk[4];
    float vmax = -3.0e38f;
#pragma unroll
    for (int q = 0; q < 4; ++q) {
        int j = threadIdx.x + q * 256;
        float s = Sr[j];
        int m = (fabsf(s) > 1e-9f);
        float e = e1r[j] + e2i;
        float l = e > 0.f ? e : 0.2f * e;
        lv[q] = l;
        mk[q] = m;
        if (m) vmax = fmaxf(vmax, l);
    }
    vmax = blockReduceMax(vmax, sm);
    float sum = 0.f;
#pragma unroll
    for (int q = 0; q < 4; ++q)
        sum += mk[q] ? __expf(lv[q] - vmax) : 0.f;
    sum = blockReduceSum(sum, sm);
    if (threadIdx.x == 0) {
        g_m[bp * Nn + i] = vmax;
        g_s[bp * Nn + i] = sum;
    }
}

// ======================= 5. fill: sparse aij values (CSC) ======================
__global__ void fill_kernel() {
    int bp = blockIdx.y, b = bp >> 2;
    int w = threadIdx.x >> 5, lane = threadIdx.x & 31;
    int j = blockIdx.x * 8 + w;
    int cnt = g_cnt[b * Nn + j];
    int pad = (cnt + 31) & ~31;
    float e1j = g_e1[bp * Nn + j];
    const unsigned short* ip = g_idx + ((size_t)b * Nn + j) * MAXS;
    float* ap = g_av + ((size_t)bp * Nn + j) * MAXS;
    for (int sb = 0; sb < pad; sb += 32) {
        int sidx = sb + lane;
        float v = 0.f;
        if (sidx < cnt) {
            int i = ip[sidx];
            float e = e1j + g_e2[bp * Nn + i];
            float l = e > 0.f ? e : 0.2f * e;
            v = __expf(l - g_m[bp * Nn + i]) / g_s[bp * Nn + i];
        }
        ap[sidx] = v;
    }
}

// ======================= 6. prop: sparse z_k = z_{k-1} @ aij ===================
// CTA = (g-block of 32, bp); smem holds input slice [1024 i][32 g] fp32 (128 KB).
// Warp per output row j: gather ~52 rows, fp32 FMA. Writes zT fp32 + bf16 hi/lo.
__global__ void __launch_bounds__(256, 1)
prop_kernel(int ks) {
    extern __shared__ float zin[];  // [1024][32]
    const int bp = blockIdx.y, b = bp >> 2, gb = blockIdx.x;
    const int tid = threadIdx.x, w = tid >> 5, lane = tid & 31;
    const size_t NN = (size_t)Nn * Nn;

    const float* src = g_zf + (size_t)bp * NN + (size_t)(ks - 1) * Gc + gb * 32;
#pragma unroll 8
    for (int r = 0; r < 32; ++r) {
        int row = r * 32 + (tid >> 3);
        int c4 = tid & 7;
        float4 v = *(const float4*)(src + (size_t)row * Nn + c4 * 4);
        *(float4*)(zin + row * 32 + c4 * 4) = v;
    }
    __syncthreads();

    for (int j = w; j < Nn; j += 8) {
        int cnt = g_cnt[b * Nn + j];
        int pad = (cnt + 31) & ~31;
        const float* ap = g_av + ((size_t)bp * Nn + j) * MAXS;
        const unsigned short* ip = g_idx + ((size_t)b * Nn + j) * MAXS;
        float acc0 = 0.f, acc1 = 0.f;
        for (int sb = 0; sb < pad; sb += 32) {
            float a = ap[sb + lane];
            int ii = ip[sb + lane];
#pragma unroll
            for (int t2 = 0; t2 < 32; t2 += 2) {
                float aa0 = __shfl_sync(0xffffffffu, a, t2);
                int i0 = __shfl_sync(0xffffffffu, ii, t2);
                float aa1 = __shfl_sync(0xffffffffu, a, t2 + 1);
                int i1 = __shfl_sync(0xffffffffu, ii, t2 + 1);
                acc0 = fmaf(aa0, zin[i0 * 32 + lane], acc0);
                acc1 = fmaf(aa1, zin[i1 * 32 + lane], acc1);
            }
        }
        float acc = acc0 + acc1;
        size_t o = ((size_t)bp * Nn + j) * Nn + (size_t)ks * Gc + gb * 32 + lane;
        g_zf[o] = acc;
        __nv_bfloat16 h, l;
        split2(acc, h, l);
        g_zh[o] = h;
        g_zl[o] = l;
    }
}

// ======================= 7. HMMA filter GEMM ===================================
// out[bp][f][n] = lrelu( fw[p] @ Z + bias ), K = kG = 1024.
// A = fw hi/lo [f][kG]; B = zT hi/lo [n][kG] (both K-major, non-trans ldmatrix).
// CTA 128(f) x 128(n), 8 warps 2x4, warp tile 64x32, BK=32, 3 stages, 2 CTA/SM.
#define TBK 32
#define NCH (Nn / TBK)
#define ASTG 16384
#define BSTG 16384
#define STG (ASTG + BSTG)
#define NSTAGE 3
#define SMEM_GEMM (NSTAGE * STG)

__global__ void __launch_bounds__(256, 2)
mma_gemm(const float* __restrict__ bias, float* __restrict__ out) {
    extern __shared__ __align__(1024) char smem[];
    uint32_t sb = smem_u32(smem);
    const int bp = blockIdx.z, p = bp & 3;
    const int m0 = blockIdx.y * 128, n0 = blockIdx.x * 128;
    const int tid = threadIdx.x, wid = tid >> 5, lane = tid & 31;
    const int warp_m = wid >> 2, warp_n = wid & 3;
    const size_t NN = (size_t)Nn * Nn;

    const __nv_bfloat16* Ah = g_fwh + (size_t)p * Fc * Nn;
    const __nv_bfloat16* Al = g_fwl + (size_t)p * Fc * Nn;
    const __nv_bfloat16* Bh = g_zh + (size_t)bp * NN;
    const __nv_bfloat16* Bl = g_zl + (size_t)bp * NN;

    float acc[4][4][4];
#pragma unroll
    for (int i = 0; i < 4; ++i)
#pragma unroll
        for (int j = 0; j < 4; ++j)
#pragma unroll
            for (int q = 0; q < 4; ++q) acc[i][j][q] = 0.f;

    auto load_stage = [&](int c, int s) {
        uint32_t base = sb + s * STG;
        int k0 = c * TBK;
#pragma unroll
        for (int i = 0; i < 4; ++i) {
            int idx = i * 256 + tid;
            int r = idx >> 3, ch = idx & 7;
            const __nv_bfloat16* srcp = ((ch < 4) ? Ah : Al) + (size_t)(m0 + r) * Nn + k0 + (ch & 3) * 8;
            cpa16(base + SWZ(r * 128 + ch * 16), srcp);
        }
#pragma unroll
        for (int i = 0; i < 4; ++i) {
            int idx = i * 256 + tid;
            int r = idx >> 3, ch = idx & 7;
            const __nv_bfloat16* srcp = ((ch < 4) ? Bh : Bl) + (size_t)(n0 + r) * Nn + k0 + (ch & 3) * 8;
            cpa16(base + ASTG + SWZ(r * 128 + ch * 16), srcp);
        }
        cpa_commit();
    };

    const int a_row = (lane & 7) + ((lane >> 3) & 1) * 8;
    const int a_k16 = lane >> 4;
    const int b_row = (lane & 7);
    const int b_par = (lane >> 3) & 1;

    load_stage(0, 0);
    load_stage(1, 1);
    for (int c = 0; c < NCH; ++c) {
        if (c + 2 < NCH) {
            load_stage(c + 2, (c + 2) % NSTAGE);
            cpa_wait2();
        } else if (c + 1 < NCH) {
            cpa_wait1();
        } else {
            cpa_wait0();
        }
        __syncthreads();
        uint32_t Abase = sb + (c % NSTAGE) * STG;
        uint32_t Bbase = Abase + ASTG;
#pragma unroll
        for (int s = 0; s < 2; ++s) {
            // B fragments: 4 n-octets, hi/lo, this k16 step
            uint32_t bh2[4][2], bl2[4][2];
#pragma unroll
            for (int o = 0; o < 4; ++o) {
                int row = warp_n * 32 + o * 8 + b_row;
                int chk = s * 2 + b_par;
                ldm_x2(bh2[o][0], bh2[o][1], Bbase + SWZ(row * 128 + chk * 16));
                ldm_x2(bl2[o][0], bl2[o][1], Bbase + SWZ(row * 128 + 64 + chk * 16));
            }
            // A fragments: 4 m16 tiles, hi/lo
            uint32_t ah[4][4], al[4][4];
#pragma unroll
            for (int mt = 0; mt < 4; ++mt) {
                int row = warp_m * 64 + mt * 16 + a_row;
                int chh = s * 2 + a_k16;
                ldm_x4(ah[mt][0], ah[mt][1], ah[mt][2], ah[mt][3],
                       Abase + SWZ(row * 128 + chh * 16));
                ldm_x4(al[mt][0], al[mt][1], al[mt][2], al[mt][3],
                       Abase + SWZ(row * 128 + 64 + chh * 16));
            }
            // three product sweeps
#pragma unroll
            for (int mt = 0; mt < 4; ++mt)
#pragma unroll
                for (int o = 0; o < 4; ++o) mma16816(acc[mt][o], ah[mt], bh2[o]);
#pragma unroll
            for (int mt = 0; mt < 4; ++mt)
#pragma unroll
                for (int o = 0; o < 4; ++o) mma16816(acc[mt][o], ah[mt], bl2[o]);
#pragma unroll
            for (int mt = 0; mt < 4; ++mt)
#pragma unroll
                for (int o = 0; o < 4; ++o) mma16816(acc[mt][o], al[mt], bh2[o]);
        }
        __syncthreads();
    }

    // epilogue: out[bp][f][n]
    float* C = out + (size_t)bp * Fc * Nn;
    const int r_base = m0 + warp_m * 64 + (lane >> 2);
    const int c_base = n0 + warp_n * 32 + (lane & 3) * 2;
#pragma unroll
    for (int mt = 0; mt < 4; ++mt)
#pragma unroll
        for (int o = 0; o < 4; ++o) {
#pragma unroll
            for (int h = 0; h < 2; ++h) {
                int r = r_base + mt * 16 + h * 8;
                int cc = c_base + o * 8;
                float bv = bias[r];
                float t0 = acc[mt][o][2 * h] + bv;
                float t1 = acc[mt][o][2 * h + 1] + bv;
                t0 = t0 > 0.f ? t0 : 0.01f * t0;
                t1 = t1 > 0.f ? t1 : 0.01f * t1;
                *(float2*)(C + (size_t)r * Nn + cc) = make_float2(t0, t1);
            }
        }
}

// ======================= launch ================================================
extern "C" void kernel_launch(void* const* d_in, const int* in_sizes, int n_in,
                              void* d_out, int out_size) {
    const float* x      = (const float*)d_in[0];
    const float* mixer  = (const float*)d_in[1];
    const float* weight = (const float*)d_in[2];
    const float* wb     = (const float*)d_in[3];
    const float* fw     = (const float*)d_in[4];
    const float* bias   = (const float*)d_in[5];
    const float* S      = (const float*)d_in[6];
    float* out = (float*)d_out;

    cudaFuncSetAttribute(mma_gemm, cudaFuncAttributeMaxDynamicSharedMemorySize, SMEM_GEMM);
    cudaFuncSetAttribute(prop_kernel, cudaFuncAttributeMaxDynamicSharedMemorySize, 131072);

    split_kernel<<<dim3(Nn / 32, Gc / 32, Bc), dim3(32, 8)>>>(x, fw);     // 1
    pe_kernel<<<dim3(Nn / 256, NBP), 256>>>(x, mixer, weight, wb);        // 2
    idx_kernel<<<dim3(Nn / 256, Bc), 256>>>(S);                           // 3
    ms_kernel<<<dim3(Nn, NBP), 256>>>(S);                                 // 4
    fill_kernel<<<dim3(Nn / 8, NBP), 256>>>();                            // 5

    for (int k = 1; k < Kc; ++k)                                          // 6,7,8
        prop_kernel<<<dim3(8, NBP), 256, 131072>>>(k);

    mma_gemm<<<dim3(Nn / 128, Fc / 128, NBP), 256, SMEM_GEMM>>>(bias, out);  // 9
}

// round 9
// speedup vs baseline: 1.1710x; 1.1710x over previous
#include <cuda_runtime.h>
#include <cuda_bf16.h>
#include <cstdint>

#define Bc 8
#define Gc 256
#define Nn 1024
#define Pc 4
#define Fc 256
#define Kc 4
#define NBP 32
#define MAXS 128

// ======================= device scratch ======================================
__device__ float g_e1[NBP * Nn];
__device__ float g_e2[NBP * Nn];
__device__ float g_m[NBP * Nn];
__device__ float g_s[NBP * Nn];
__device__ int g_cnt[Bc * Nn];
__device__ unsigned short g_idx[(size_t)Bc * Nn * MAXS];    // 2 MB
__device__ float2 g_avi[(size_t)NBP * Nn * MAXS];           // 32 MB (value, i-bits)
__device__ float g_zf[(size_t)NBP * Nn * Nn];               // 128 MB zT fp32 [bp][n][kG]
__device__ __nv_bfloat16 g_zh[(size_t)NBP * Nn * Nn];       // 64 MB zT hi
__device__ __nv_bfloat16 g_zl[(size_t)NBP * Nn * Nn];       // 64 MB zT lo
__device__ __nv_bfloat16 g_fwh[(size_t)Pc * Fc * Kc * Gc];
__device__ __nv_bfloat16 g_fwl[(size_t)Pc * Fc * Kc * Gc];

__device__ __forceinline__ void split2(float v, __nv_bfloat16& h, __nv_bfloat16& l) {
    h = __float2bfloat16(v);
    l = __float2bfloat16(v - __bfloat162float(h));
}

// ======================= helpers =============================================
__device__ __forceinline__ uint32_t smem_u32(const void* p) {
    uint32_t a;
    asm("{ .reg .u64 t; cvta.to.shared.u64 t, %1; cvt.u32.u64 %0, t; }" : "=r"(a) : "l"(p));
    return a;
}
__device__ __forceinline__ void cpa16(uint32_t dst, const void* src) {
    asm volatile("cp.async.cg.shared.global [%0], [%1], 16;" :: "r"(dst), "l"(src));
}
__device__ __forceinline__ void cpa_commit() { asm volatile("cp.async.commit_group;" ::: "memory"); }
__device__ __forceinline__ void cpa_wait2() { asm volatile("cp.async.wait_group 2;" ::: "memory"); }
__device__ __forceinline__ void cpa_wait1() { asm volatile("cp.async.wait_group 1;" ::: "memory"); }
__device__ __forceinline__ void cpa_wait0() { asm volatile("cp.async.wait_group 0;" ::: "memory"); }

#define SWZ(off) ((off) ^ (((off) >> 3) & 0x70))

__device__ __forceinline__ void ldm_x4(uint32_t& r0, uint32_t& r1, uint32_t& r2, uint32_t& r3,
                                       uint32_t addr) {
    asm volatile("ldmatrix.sync.aligned.m8n8.x4.shared.b16 {%0,%1,%2,%3}, [%4];"
                 : "=r"(r0), "=r"(r1), "=r"(r2), "=r"(r3) : "r"(addr));
}
__device__ __forceinline__ void ldm_x2(uint32_t& r0, uint32_t& r1, uint32_t addr) {
    asm volatile("ldmatrix.sync.aligned.m8n8.x2.shared.b16 {%0,%1}, [%2];"
                 : "=r"(r0), "=r"(r1) : "r"(addr));
}
__device__ __forceinline__ void mma16816(float* c, const uint32_t* a, const uint32_t* b) {
    asm volatile(
        "mma.sync.aligned.m16n8k16.row.col.f32.bf16.bf16.f32 "
        "{%0,%1,%2,%3}, {%4,%5,%6,%7}, {%8,%9}, {%0,%1,%2,%3};"
        : "+f"(c[0]), "+f"(c[1]), "+f"(c[2]), "+f"(c[3])
        : "r"(a[0]), "r"(a[1]), "r"(a[2]), "r"(a[3]), "r"(b[0]), "r"(b[1]));
}

// ======================= 1. idx: CSC pattern of S[b], warp per column =========
__global__ void idx_kernel(const float* __restrict__ S) {
    __shared__ unsigned short tmp[8][1024];
    int b = blockIdx.y;
    int w = threadIdx.x >> 5, lane = threadIdx.x & 31;
    int j = blockIdx.x * 8 + w;
    const float* Sb = S + (size_t)b * Nn * Nn + j;
    int r0 = lane * 32;
    int c = 0;
#pragma unroll 4
    for (int r = 0; r < 32; ++r) {
        float s = __ldg(Sb + (size_t)(r0 + r) * Nn);
        if (fabsf(s) > 1e-9f) tmp[w][r0 + c++] = (unsigned short)(r0 + r);
    }
    int incl = c;
#pragma unroll
    for (int o = 1; o < 32; o <<= 1) {
        int t = __shfl_up_sync(0xffffffffu, incl, o);
        if (lane >= o) incl += t;
    }
    int excl = incl - c;
    int total = __shfl_sync(0xffffffffu, incl, 31);
    unsigned short* ipout = g_idx + ((size_t)b * Nn + j) * MAXS;
    for (int t = 0; t < c; ++t) {
        int pos = excl + t;
        if (pos < MAXS) ipout[pos] = tmp[w][r0 + t];
    }
    if (lane == 0) g_cnt[b * Nn + j] = total < MAXS ? total : MAXS;
}

// ======================= 2. pe: e1/e2[bp][n] ===================================
__global__ void pe_kernel(const float* __restrict__ x,
                          const float* __restrict__ mixer,
                          const float* __restrict__ weight,
                          const float* __restrict__ wb) {
    int bp = blockIdx.y;
    int b = bp >> 2, p = bp & 3;
    int tid = threadIdx.x;
    __shared__ float s1[Gc], s2[Gc], sc[2];
    {
        int g = tid;
        float v1 = 0.f, v2 = 0.f;
        const float* mw1 = mixer + p * 2 * Fc;
        const float* mw2 = mw1 + Fc;
#pragma unroll 8
        for (int f = 0; f < Fc; ++f) {
            float w = weight[((size_t)(p * Fc + f)) * Gc + g];
            v1 = fmaf(mw1[f], w, v1);
            v2 = fmaf(mw2[f], w, v2);
        }
        s1[g] = v1;
        s2[g] = v2;
        if (g == 0) {
            float c1 = 0.f, c2 = 0.f;
            for (int f = 0; f < Fc; ++f) {
                c1 = fmaf(mw1[f], wb[p * Fc + f], c1);
                c2 = fmaf(mw2[f], wb[p * Fc + f], c2);
            }
            sc[0] = c1;
            sc[1] = c2;
        }
    }
    __syncthreads();
    int n = blockIdx.x * blockDim.x + tid;
    const float* xb = x + (size_t)b * Gc * Nn + n;
    float a1 = 0.f, a2 = 0.f;
#pragma unroll 8
    for (int g = 0; g < Gc; ++g) {
        float xv = xb[(size_t)g * Nn];
        a1 = fmaf(s1[g], xv, a1);
        a2 = fmaf(s2[g], xv, a2);
    }
    g_e1[bp * Nn + n] = a1 + sc[0];
    g_e2[bp * Nn + n] = a2 + sc[1];
}

// ======================= reductions ==========================================
__device__ __forceinline__ float blockReduceMax(float v, float* sm) {
#pragma unroll
    for (int o = 16; o; o >>= 1) v = fmaxf(v, __shfl_xor_sync(0xffffffffu, v, o));
    if ((threadIdx.x & 31) == 0) sm[threadIdx.x >> 5] = v;
    __syncthreads();
    if (threadIdx.x < 32) {
        float t = (threadIdx.x < 8) ? sm[threadIdx.x] : -3.0e38f;
#pragma unroll
        for (int o = 4; o; o >>= 1) t = fmaxf(t, __shfl_xor_sync(0xffffffffu, t, o));
        if (threadIdx.x == 0) sm[0] = t;
    }
    __syncthreads();
    float r = sm[0];
    __syncthreads();
    return r;
}
__device__ __forceinline__ float blockReduceSum(float v, float* sm) {
#pragma unroll
    for (int o = 16; o; o >>= 1) v += __shfl_xor_sync(0xffffffffu, v, o);
    if ((threadIdx.x & 31) == 0) sm[threadIdx.x >> 5] = v;
    __syncthreads();
    if (threadIdx.x < 32) {
        float t = (threadIdx.x < 8) ? sm[threadIdx.x] : 0.f;
#pragma unroll
        for (int o = 4; o; o >>= 1) t += __shfl_xor_sync(0xffffffffu, t, o);
        if (threadIdx.x == 0) sm[0] = t;
    }
    __syncthreads();
    float r = sm[0];
    __syncthreads();
    return r;
}

// ======================= 3. ms: per-row softmax stats ==========================
__global__ void ms_kernel(const float* __restrict__ S) {
    int i = blockIdx.x, bp = blockIdx.y, b = bp >> 2;
    __shared__ float sm[8];
    float e2i = g_e2[bp * Nn + i];
    const float* e1r = g_e1 + bp * Nn;
    const float* Sr = S + (size_t)b * Nn * Nn + (size_t)i * Nn;
    float lv[4];
    int mk[4];
    float vmax = -3.0e38f;
#pragma unroll
    for (int q = 0; q < 4; ++q) {
        int j = threadIdx.x + q * 256;
        float s = Sr[j];
        int m = (fabsf(s) > 1e-9f);
        float e = e1r[j] + e2i;
        float l = e > 0.f ? e : 0.2f * e;
        lv[q] = l;
        mk[q] = m;
        if (m) vmax = fmaxf(vmax, l);
    }
    vmax = blockReduceMax(vmax, sm);
    float sum = 0.f;
#pragma unroll
    for (int q = 0; q < 4; ++q)
        sum += mk[q] ? __expf(lv[q] - vmax) : 0.f;
    sum = blockReduceSum(sum, sm);
    if (threadIdx.x == 0) {
        g_m[bp * Nn + i] = vmax;
        g_s[bp * Nn + i] = sum;
    }
}

// ======================= 4. fill: packed sparse values (CSC) ===================
__global__ void fill_kernel() {
    int bp = blockIdx.y, b = bp >> 2;
    int w = threadIdx.x >> 5, lane = threadIdx.x & 31;
    int j = blockIdx.x * 8 + w;
    int cnt = g_cnt[b * Nn + j];
    float e1j = g_e1[bp * Nn + j];
    const unsigned short* ip = g_idx + ((size_t)b * Nn + j) * MAXS;
    float2* ap = g_avi + ((size_t)bp * Nn + j) * MAXS;
    for (int s = lane; s < cnt; s += 32) {
        int i = ip[s];
        float e = e1j + g_e2[bp * Nn + i];
        float l = e > 0.f ? e : 0.2f * e;
        float v = __expf(l - g_m[bp * Nn + i]) / g_s[bp * Nn + i];
        ap[s] = make_float2(v, __int_as_float(i));
    }
}

// ======================= 5. split: x -> zT slice0 (fp32 + hi/lo), fw split ====
__global__ void split_kernel(const float* __restrict__ x, const float* __restrict__ fw) {
    int b = blockIdx.z;
    int g0 = blockIdx.y * 32, n0 = blockIdx.x * 32;
    __shared__ float t[32][33];
    int tx = threadIdx.x, ty = threadIdx.y;
    const float* xp = x + ((size_t)b * Gc + g0) * Nn + n0;
#pragma unroll
    for (int q = 0; q < 4; ++q) {
        int g = ty + q * 8;
        t[g][tx] = xp[(size_t)g * Nn + tx];
    }
    __syncthreads();
#pragma unroll
    for (int q = 0; q < 4; ++q) {
        int nn = ty + q * 8;
        float v = t[tx][nn];
        __nv_bfloat16 h, l;
        split2(v, h, l);
#pragma unroll
        for (int p = 0; p < 4; ++p) {
            size_t o = (((size_t)(b * 4 + p) * Nn) + n0 + nn) * Nn + g0 + tx;
            g_zf[o] = v;
            g_zh[o] = h;
            g_zl[o] = l;
        }
    }
    const int FT = Pc * Fc * Kc * Gc;
    int tot = gridDim.x * gridDim.y * gridDim.z * 256;
    int gid = ((blockIdx.z * gridDim.y + blockIdx.y) * gridDim.x + blockIdx.x) * 256 + ty * 32 + tx;
    for (int i = gid; i < FT; i += tot) {
        __nv_bfloat16 h, l;
        split2(fw[i], h, l);
        g_fwh[i] = h;
        g_fwl[i] = l;
    }
}

// ======================= 6. prop v2: sparse z_k = z_{k-1} @ aij ================
// CTA = (g-block of 32, bp); smem: zT input slice [1024 i][32 g] fp32 (128 KB).
// lane = (jj 0..3, gq 0..7): 4 j's per warp, float4 of g per thread.
// Per nnz s: 1 broadcast LDG.64 (value,i) + 1 LDS.128 + 4 FMA. No shuffles.
__global__ void __launch_bounds__(256, 1)
prop_kernel(int ks) {
    extern __shared__ float zin[];  // [1024][32]
    const int bp = blockIdx.y, b = bp >> 2, gb = blockIdx.x;
    const int tid = threadIdx.x, w = tid >> 5, lane = tid & 31;
    const int jj = lane >> 3, gq = lane & 7;
    const size_t NN = (size_t)Nn * Nn;

    const float* src = g_zf + (size_t)bp * NN + (size_t)(ks - 1) * Gc + (size_t)gb * 32;
#pragma unroll 8
    for (int r = 0; r < 32; ++r) {
        int row = r * 32 + (tid >> 3);
        int c4 = tid & 7;
        float4 v = *(const float4*)(src + (size_t)row * Nn + c4 * 4);
        *(float4*)(zin + row * 32 + c4 * 4) = v;
    }
    __syncthreads();

    for (int jb = w * 4; jb < Nn; jb += 32) {
        int j = jb + jj;
        int cnt = g_cnt[b * Nn + j];
        const float2* ap = g_avi + ((size_t)bp * Nn + j) * MAXS;
        float4 acc = make_float4(0.f, 0.f, 0.f, 0.f);
        float2 nxt = (cnt > 0) ? __ldg(ap) : make_float2(0.f, 0.f);
        for (int s = 0; s < cnt; ++s) {
            float2 cur = nxt;
            if (s + 1 < cnt) nxt = __ldg(ap + s + 1);
            int i = __float_as_int(cur.y);
            const float4 zv = *(const float4*)(zin + i * 32 + gq * 4);
            acc.x = fmaf(cur.x, zv.x, acc.x);
            acc.y = fmaf(cur.x, zv.y, acc.y);
            acc.z = fmaf(cur.x, zv.z, acc.z);
            acc.w = fmaf(cur.x, zv.w, acc.w);
        }
        size_t o = ((size_t)bp * Nn + j) * Nn + (size_t)ks * Gc + gb * 32 + gq * 4;
        *(float4*)(g_zf + o) = acc;
        __nv_bfloat16 h0, l0, h1, l1, h2, l2, h3, l3;
        split2(acc.x, h0, l0);
        split2(acc.y, h1, l1);
        split2(acc.z, h2, l2);
        split2(acc.w, h3, l3);
        __nv_bfloat162 ph01, ph23, pl01, pl23;
        ph01.x = h0; ph01.y = h1; ph23.x = h2; ph23.y = h3;
        pl01.x = l0; pl01.y = l1; pl23.x = l2; pl23.y = l3;
        *(__nv_bfloat162*)(g_zh + o) = ph01;
        *(__nv_bfloat162*)(g_zh + o + 2) = ph23;
        *(__nv_bfloat162*)(g_zl + o) = pl01;
        *(__nv_bfloat162*)(g_zl + o + 2) = pl23;
    }
}

// ======================= 7. HMMA filter GEMM ===================================
#define TBK 32
#define NCH (Nn / TBK)
#define ASTG 16384
#define BSTG 16384
#define STG (ASTG + BSTG)
#define NSTAGE 3
#define SMEM_GEMM (NSTAGE * STG)

__global__ void __launch_bounds__(256, 2)
mma_gemm(const float* __restrict__ bias, float* __restrict__ out) {
    extern __shared__ __align__(1024) char smem[];
    uint32_t sb = smem_u32(smem);
    const int bp = blockIdx.z, p = bp & 3;
    const int m0 = blockIdx.y * 128, n0 = blockIdx.x * 128;
    const int tid = threadIdx.x, wid = tid >> 5, lane = tid & 31;
    const int warp_m = wid >> 2, warp_n = wid & 3;
    const size_t NN = (size_t)Nn * Nn;

    const __nv_bfloat16* Ah = g_fwh + (size_t)p * Fc * Nn;
    const __nv_bfloat16* Al = g_fwl + (size_t)p * Fc * Nn;
    const __nv_bfloat16* Bh = g_zh + (size_t)bp * NN;
    const __nv_bfloat16* Bl = g_zl + (size_t)bp * NN;

    float acc[4][4][4];
#pragma unroll
    for (int i = 0; i < 4; ++i)
#pragma unroll
        for (int j = 0; j < 4; ++j)
#pragma unroll
            for (int q = 0; q < 4; ++q) acc[i][j][q] = 0.f;

    auto load_stage = [&](int c, int s) {
        uint32_t base = sb + s * STG;
        int k0 = c * TBK;
#pragma unroll
        for (int i = 0; i < 4; ++i) {
            int idx = i * 256 + tid;
            int r = idx >> 3, ch = idx & 7;
            const __nv_bfloat16* srcp = ((ch < 4) ? Ah : Al) + (size_t)(m0 + r) * Nn + k0 + (ch & 3) * 8;
            cpa16(base + SWZ(r * 128 + ch * 16), srcp);
        }
#pragma unroll
        for (int i = 0; i < 4; ++i) {
            int idx = i * 256 + tid;
            int r = idx >> 3, ch = idx & 7;
            const __nv_bfloat16* srcp = ((ch < 4) ? Bh : Bl) + (size_t)(n0 + r) * Nn + k0 + (ch & 3) * 8;
            cpa16(base + ASTG + SWZ(r * 128 + ch * 16), srcp);
        }
        cpa_commit();
    };

    const int a_row = (lane & 7) + ((lane >> 3) & 1) * 8;
    const int a_k16 = lane >> 4;
    const int b_row = (lane & 7);
    const int b_par = (lane >> 3) & 1;

    load_stage(0, 0);
    load_stage(1, 1);
    for (int c = 0; c < NCH; ++c) {
        if (c + 2 < NCH) {
            load_stage(c + 2, (c + 2) % NSTAGE);
            cpa_wait2();
        } else if (c + 1 < NCH) {
            cpa_wait1();
        } else {
            cpa_wait0();
        }
        __syncthreads();
        uint32_t Abase = sb + (c % NSTAGE) * STG;
        uint32_t Bbase = Abase + ASTG;
#pragma unroll
        for (int s = 0; s < 2; ++s) {
            uint32_t bh2[4][2], bl2[4][2];
#pragma unroll
            for (int o = 0; o < 4; ++o) {
                int row = warp_n * 32 + o * 8 + b_row;
                int chk = s * 2 + b_par;
                ldm_x2(bh2[o][0], bh2[o][1], Bbase + SWZ(row * 128 + chk * 16));
                ldm_x2(bl2[o][0], bl2[o][1], Bbase + SWZ(row * 128 + 64 + chk * 16));
            }
            uint32_t ah[4][4], al[4][4];
#pragma unroll
            for (int mt = 0; mt < 4; ++mt) {
                int row = warp_m * 64 + mt * 16 + a_row;
                int chh = s * 2 + a_k16;
                ldm_x4(ah[mt][0], ah[mt][1], ah[mt][2], ah[mt][3],
                       Abase + SWZ(row * 128 + chh * 16));
                ldm_x4(al[mt][0], al[mt][1], al[mt][2], al[mt][3],
                       Abase + SWZ(row * 128 + 64 + chh * 16));
            }
#pragma unroll
            for (int mt = 0; mt < 4; ++mt)
#pragma unroll
                for (int o = 0; o < 4; ++o) mma16816(acc[mt][o], ah[mt], bh2[o]);
#pragma unroll
            for (int mt = 0; mt < 4; ++mt)
#pragma unroll
                for (int o = 0; o < 4; ++o) mma16816(acc[mt][o], ah[mt], bl2[o]);
#pragma unroll
            for (int mt = 0; mt < 4; ++mt)
#pragma unroll
                for (int o = 0; o < 4; ++o) mma16816(acc[mt][o], al[mt], bh2[o]);
        }
        __syncthreads();
    }

    float* C = out + (size_t)bp * Fc * Nn;
    const int r_base = m0 + warp_m * 64 + (lane >> 2);
    const int c_base = n0 + warp_n * 32 + (lane & 3) * 2;
#pragma unroll
    for (int mt = 0; mt < 4; ++mt)
#pragma unroll
        for (int o = 0; o < 4; ++o) {
#pragma unroll
            for (int h = 0; h < 2; ++h) {
                int r = r_base + mt * 16 + h * 8;
                int cc = c_base + o * 8;
                float bv = bias[r];
                float t0 = acc[mt][o][2 * h] + bv;
                float t1 = acc[mt][o][2 * h + 1] + bv;
                t0 = t0 > 0.f ? t0 : 0.01f * t0;
                t1 = t1 > 0.f ? t1 : 0.01f * t1;
                *(float2*)(C + (size_t)r * Nn + cc) = make_float2(t0, t1);
            }
        }
}

// ======================= launch ================================================
extern "C" void kernel_launch(void* const* d_in, const int* in_sizes, int n_in,
                              void* d_out, int out_size) {
    const float* x      = (const float*)d_in[0];
    const float* mixer  = (const float*)d_in[1];
    const float* weight = (const float*)d_in[2];
    const float* wb     = (const float*)d_in[3];
    const float* fw     = (const float*)d_in[4];
    const float* bias   = (const float*)d_in[5];
    const float* S      = (const float*)d_in[6];
    float* out = (float*)d_out;

    cudaFuncSetAttribute(mma_gemm, cudaFuncAttributeMaxDynamicSharedMemorySize, SMEM_GEMM);
    cudaFuncSetAttribute(prop_kernel, cudaFuncAttributeMaxDynamicSharedMemorySize, 131072);

    idx_kernel<<<dim3(Nn / 8, Bc), 256>>>(S);                            // 1
    pe_kernel<<<dim3(Nn / 256, NBP), 256>>>(x, mixer, weight, wb);       // 2
    ms_kernel<<<dim3(Nn, NBP), 256>>>(S);                                // 3
    fill_kernel<<<dim3(Nn / 8, NBP), 256>>>();                           // 4
    split_kernel<<<dim3(Nn / 32, Gc / 32, Bc), dim3(32, 8)>>>(x, fw);    // 5

    for (int k = 1; k < Kc; ++k)                                         // 6,7,8
        prop_kernel<<<dim3(8, NBP), 256, 131072>>>(k);

    mma_gemm<<<dim3(Nn / 128, Fc / 128, NBP), 256, SMEM_GEMM>>>(bias, out);  // 9
}

// round 10
// speedup vs baseline: 1.9133x; 1.6339x over previous
#include <cuda_runtime.h>
#include <cuda_bf16.h>
#include <cstdint>

#define Bc 8
#define Gc 256
#define Nn 1024
#define Pc 4
#define Fc 256
#define Kc 4
#define NBP 32
#define MAXS 128
#define PF 16

// ======================= device scratch ======================================
__device__ float g_e1[NBP * Nn];
__device__ float g_e2[NBP * Nn];
__device__ float g_m[NBP * Nn];
__device__ float g_s[NBP * Nn];
__device__ int g_cnt[Bc * Nn];
__device__ unsigned short g_idx[(size_t)Bc * Nn * MAXS];    // 2 MB
__device__ float2 g_avi[(size_t)NBP * Nn * MAXS];           // 32 MB (value, i-bits)
__device__ float g_zf[(size_t)NBP * Nn * Nn];               // 128 MB zT fp32 [bp][n][kG]
__device__ __nv_bfloat16 g_zh[(size_t)NBP * Nn * Nn];       // 64 MB zT hi
__device__ __nv_bfloat16 g_zl[(size_t)NBP * Nn * Nn];       // 64 MB zT lo
__device__ __nv_bfloat16 g_fwh[(size_t)Pc * Fc * Kc * Gc];
__device__ __nv_bfloat16 g_fwl[(size_t)Pc * Fc * Kc * Gc];

__device__ __forceinline__ void split2(float v, __nv_bfloat16& h, __nv_bfloat16& l) {
    h = __float2bfloat16(v);
    l = __float2bfloat16(v - __bfloat162float(h));
}

// ======================= helpers =============================================
__device__ __forceinline__ uint32_t smem_u32(const void* p) {
    uint32_t a;
    asm("{ .reg .u64 t; cvta.to.shared.u64 t, %1; cvt.u32.u64 %0, t; }" : "=r"(a) : "l"(p));
    return a;
}
__device__ __forceinline__ void cpa16(uint32_t dst, const void* src) {
    asm volatile("cp.async.cg.shared.global [%0], [%1], 16;" :: "r"(dst), "l"(src));
}
__device__ __forceinline__ void cpa_commit() { asm volatile("cp.async.commit_group;" ::: "memory"); }
__device__ __forceinline__ void cpa_wait2() { asm volatile("cp.async.wait_group 2;" ::: "memory"); }
__device__ __forceinline__ void cpa_wait1() { asm volatile("cp.async.wait_group 1;" ::: "memory"); }
__device__ __forceinline__ void cpa_wait0() { asm volatile("cp.async.wait_group 0;" ::: "memory"); }

#define SWZ(off) ((off) ^ (((off) >> 3) & 0x70))

__device__ __forceinline__ void ldm_x4(uint32_t& r0, uint32_t& r1, uint32_t& r2, uint32_t& r3,
                                       uint32_t addr) {
    asm volatile("ldmatrix.sync.aligned.m8n8.x4.shared.b16 {%0,%1,%2,%3}, [%4];"
                 : "=r"(r0), "=r"(r1), "=r"(r2), "=r"(r3) : "r"(addr));
}
__device__ __forceinline__ void ldm_x2(uint32_t& r0, uint32_t& r1, uint32_t addr) {
    asm volatile("ldmatrix.sync.aligned.m8n8.x2.shared.b16 {%0,%1}, [%2];"
                 : "=r"(r0), "=r"(r1) : "r"(addr));
}
__device__ __forceinline__ void mma16816(float* c, const uint32_t* a, const uint32_t* b) {
    asm volatile(
        "mma.sync.aligned.m16n8k16.row.col.f32.bf16.bf16.f32 "
        "{%0,%1,%2,%3}, {%4,%5,%6,%7}, {%8,%9}, {%0,%1,%2,%3};"
        : "+f"(c[0]), "+f"(c[1]), "+f"(c[2]), "+f"(c[3])
        : "r"(a[0]), "r"(a[1]), "r"(a[2]), "r"(a[3]), "r"(b[0]), "r"(b[1]));
}

// ======================= 1. idx: CSC pattern of S[b], warp per column =========
__global__ void idx_kernel(const float* __restrict__ S) {
    __shared__ unsigned short tmp[8][1024];
    int b = blockIdx.y;
    int w = threadIdx.x >> 5, lane = threadIdx.x & 31;
    int j = blockIdx.x * 8 + w;
    const float* Sb = S + (size_t)b * Nn * Nn + j;
    int r0 = lane * 32;
    int c = 0;
#pragma unroll 4
    for (int r = 0; r < 32; ++r) {
        float s = __ldg(Sb + (size_t)(r0 + r) * Nn);
        if (fabsf(s) > 1e-9f) tmp[w][r0 + c++] = (unsigned short)(r0 + r);
    }
    int incl = c;
#pragma unroll
    for (int o = 1; o < 32; o <<= 1) {
        int t = __shfl_up_sync(0xffffffffu, incl, o);
        if (lane >= o) incl += t;
    }
    int excl = incl - c;
    int total = __shfl_sync(0xffffffffu, incl, 31);
    unsigned short* ipout = g_idx + ((size_t)b * Nn + j) * MAXS;
    for (int t = 0; t < c; ++t) {
        int pos = excl + t;
        if (pos < MAXS) ipout[pos] = tmp[w][r0 + t];
    }
    if (lane == 0) g_cnt[b * Nn + j] = total < MAXS ? total : MAXS;
}

// ======================= 2. pe: e1/e2[bp][n] ===================================
__global__ void pe_kernel(const float* __restrict__ x,
                          const float* __restrict__ mixer,
                          const float* __restrict__ weight,
                          const float* __restrict__ wb) {
    int bp = blockIdx.y;
    int b = bp >> 2, p = bp & 3;
    int tid = threadIdx.x;
    __shared__ float s1[Gc], s2[Gc], sc[2];
    {
        int g = tid;
        float v1 = 0.f, v2 = 0.f;
        const float* mw1 = mixer + p * 2 * Fc;
        const float* mw2 = mw1 + Fc;
#pragma unroll 8
        for (int f = 0; f < Fc; ++f) {
            float w = weight[((size_t)(p * Fc + f)) * Gc + g];
            v1 = fmaf(mw1[f], w, v1);
            v2 = fmaf(mw2[f], w, v2);
        }
        s1[g] = v1;
        s2[g] = v2;
        if (g == 0) {
            float c1 = 0.f, c2 = 0.f;
            for (int f = 0; f < Fc; ++f) {
                c1 = fmaf(mw1[f], wb[p * Fc + f], c1);
                c2 = fmaf(mw2[f], wb[p * Fc + f], c2);
            }
            sc[0] = c1;
            sc[1] = c2;
        }
    }
    __syncthreads();
    int n = blockIdx.x * blockDim.x + tid;
    const float* xb = x + (size_t)b * Gc * Nn + n;
    float a1 = 0.f, a2 = 0.f;
#pragma unroll 8
    for (int g = 0; g < Gc; ++g) {
        float xv = xb[(size_t)g * Nn];
        a1 = fmaf(s1[g], xv, a1);
        a2 = fmaf(s2[g], xv, a2);
    }
    g_e1[bp * Nn + n] = a1 + sc[0];
    g_e2[bp * Nn + n] = a2 + sc[1];
}

// ======================= reductions ==========================================
__device__ __forceinline__ float blockReduceMax(float v, float* sm) {
#pragma unroll
    for (int o = 16; o; o >>= 1) v = fmaxf(v, __shfl_xor_sync(0xffffffffu, v, o));
    if ((threadIdx.x & 31) == 0) sm[threadIdx.x >> 5] = v;
    __syncthreads();
    if (threadIdx.x < 32) {
        float t = (threadIdx.x < 8) ? sm[threadIdx.x] : -3.0e38f;
#pragma unroll
        for (int o = 4; o; o >>= 1) t = fmaxf(t, __shfl_xor_sync(0xffffffffu, t, o));
        if (threadIdx.x == 0) sm[0] = t;
    }
    __syncthreads();
    float r = sm[0];
    __syncthreads();
    return r;
}
__device__ __forceinline__ float blockReduceSum(float v, float* sm) {
#pragma unroll
    for (int o = 16; o; o >>= 1) v += __shfl_xor_sync(0xffffffffu, v, o);
    if ((threadIdx.x & 31) == 0) sm[threadIdx.x >> 5] = v;
    __syncthreads();
    if (threadIdx.x < 32) {
        float t = (threadIdx.x < 8) ? sm[threadIdx.x] : 0.f;
#pragma unroll
        for (int o = 4; o; o >>= 1) t += __shfl_xor_sync(0xffffffffu, t, o);
        if (threadIdx.x == 0) sm[0] = t;
    }
    __syncthreads();
    float r = sm[0];
    __syncthreads();
    return r;
}

// ======================= 3. ms: per-row softmax stats ==========================
__global__ void ms_kernel(const float* __restrict__ S) {
    int i = blockIdx.x, bp = blockIdx.y, b = bp >> 2;
    __shared__ float sm[8];
    float e2i = g_e2[bp * Nn + i];
    const float* e1r = g_e1 + bp * Nn;
    const float* Sr = S + (size_t)b * Nn * Nn + (size_t)i * Nn;
    float lv[4];
    int mk[4];
    float vmax = -3.0e38f;
#pragma unroll
    for (int q = 0; q < 4; ++q) {
        int j = threadIdx.x + q * 256;
        float s = Sr[j];
        int m = (fabsf(s) > 1e-9f);
        float e = e1r[j] + e2i;
        float l = e > 0.f ? e : 0.2f * e;
        lv[q] = l;
        mk[q] = m;
        if (m) vmax = fmaxf(vmax, l);
    }
    vmax = blockReduceMax(vmax, sm);
    float sum = 0.f;
#pragma unroll
    for (int q = 0; q < 4; ++q)
        sum += mk[q] ? __expf(lv[q] - vmax) : 0.f;
    sum = blockReduceSum(sum, sm);
    if (threadIdx.x == 0) {
        g_m[bp * Nn + i] = vmax;
        g_s[bp * Nn + i] = sum;
    }
}

// ======================= 4. fill: packed sparse values, zero-padded to 16 =====
__global__ void fill_kernel() {
    int bp = blockIdx.y, b = bp >> 2;
    int w = threadIdx.x >> 5, lane = threadIdx.x & 31;
    int j = blockIdx.x * 8 + w;
    int cnt = g_cnt[b * Nn + j];
    int cntp = (cnt + PF - 1) & ~(PF - 1);
    float e1j = g_e1[bp * Nn + j];
    const unsigned short* ip = g_idx + ((size_t)b * Nn + j) * MAXS;
    float2* ap = g_avi + ((size_t)bp * Nn + j) * MAXS;
    for (int s = lane; s < cntp; s += 32) {
        float2 o = make_float2(0.f, __int_as_float(0));
        if (s < cnt) {
            int i = ip[s];
            float e = e1j + g_e2[bp * Nn + i];
            float l = e > 0.f ? e : 0.2f * e;
            o = make_float2(__expf(l - g_m[bp * Nn + i]) / g_s[bp * Nn + i], __int_as_float(i));
        }
        ap[s] = o;
    }
}

// ======================= 5. split: x -> zT slice0 (fp32 + hi/lo), fw split ====
__global__ void split_kernel(const float* __restrict__ x, const float* __restrict__ fw) {
    int b = blockIdx.z;
    int g0 = blockIdx.y * 32, n0 = blockIdx.x * 32;
    __shared__ float t[32][33];
    int tx = threadIdx.x, ty = threadIdx.y;
    const float* xp = x + ((size_t)b * Gc + g0) * Nn + n0;
#pragma unroll
    for (int q = 0; q < 4; ++q) {
        int g = ty + q * 8;
        t[g][tx] = xp[(size_t)g * Nn + tx];
    }
    __syncthreads();
#pragma unroll
    for (int q = 0; q < 4; ++q) {
        int nn = ty + q * 8;
        float v = t[tx][nn];
        __nv_bfloat16 h, l;
        split2(v, h, l);
#pragma unroll
        for (int p = 0; p < 4; ++p) {
            size_t o = (((size_t)(b * 4 + p) * Nn) + n0 + nn) * Nn + g0 + tx;
            g_zf[o] = v;
            g_zh[o] = h;
            g_zl[o] = l;
        }
    }
    const int FT = Pc * Fc * Kc * Gc;
    int tot = gridDim.x * gridDim.y * gridDim.z * 256;
    int gid = ((blockIdx.z * gridDim.y + blockIdx.y) * gridDim.x + blockIdx.x) * 256 + ty * 32 + tx;
    for (int i = gid; i < FT; i += tot) {
        __nv_bfloat16 h, l;
        split2(fw[i], h, l);
        g_fwh[i] = h;
        g_fwl[i] = l;
    }
}

// ======================= 6. prop v3: sparse z_k = z_{k-1} @ aij ================
// CTA = (g-block of 32, bp); smem: zT input slice [1024 i][32 g] fp32 (128 KB).
// lane = (jj 0..3, gq 0..7): 4 j's per warp, float4 of g per thread.
// nnz stream software-pipelined PF=16 deep (MLP 16), two FMA chains.
__global__ void __launch_bounds__(256, 1)
prop_kernel(int ks) {
    extern __shared__ float zin[];  // [1024][32]
    const int bp = blockIdx.y, b = bp >> 2, gb = blockIdx.x;
    const int tid = threadIdx.x, w = tid >> 5, lane = tid & 31;
    const int jj = lane >> 3, gq = lane & 7;
    const size_t NN = (size_t)Nn * Nn;

    const float* src = g_zf + (size_t)bp * NN + (size_t)(ks - 1) * Gc + (size_t)gb * 32;
#pragma unroll 8
    for (int r = 0; r < 32; ++r) {
        int row = r * 32 + (tid >> 3);
        int c4 = tid & 7;
        float4 v = *(const float4*)(src + (size_t)row * Nn + c4 * 4);
        *(float4*)(zin + row * 32 + c4 * 4) = v;
    }
    __syncthreads();

    for (int jb = w * 4; jb < Nn; jb += 32) {
        int j = jb + jj;
        int cnt = g_cnt[b * Nn + j];
        int cntp = (cnt + PF - 1) & ~(PF - 1);
        const float2* ap = g_avi + ((size_t)bp * Nn + j) * MAXS;
        float2 pre[PF];
#pragma unroll
        for (int q = 0; q < PF; ++q)
            pre[q] = (q < cntp) ? __ldg(ap + q) : make_float2(0.f, __int_as_float(0));
        float4 acc0 = make_float4(0.f, 0.f, 0.f, 0.f);
        float4 acc1 = make_float4(0.f, 0.f, 0.f, 0.f);
        for (int s0 = 0; s0 < cntp; s0 += PF) {
            float2 cur[PF];
#pragma unroll
            for (int q = 0; q < PF; ++q) cur[q] = pre[q];
#pragma unroll
            for (int q = 0; q < PF; ++q) {
                int sn = s0 + PF + q;
                pre[q] = (sn < cntp) ? __ldg(ap + sn) : make_float2(0.f, __int_as_float(0));
            }
#pragma unroll
            for (int q = 0; q < PF; ++q) {
                int i = __float_as_int(cur[q].y);
                float a = cur[q].x;
                const float4 zv = *(const float4*)(zin + i * 32 + gq * 4);
                if (q & 1) {
                    acc1.x = fmaf(a, zv.x, acc1.x);
                    acc1.y = fmaf(a, zv.y, acc1.y);
                    acc1.z = fmaf(a, zv.z, acc1.z);
                    acc1.w = fmaf(a, zv.w, acc1.w);
                } else {
                    acc0.x = fmaf(a, zv.x, acc0.x);
                    acc0.y = fmaf(a, zv.y, acc0.y);
                    acc0.z = fmaf(a, zv.z, acc0.z);
                    acc0.w = fmaf(a, zv.w, acc0.w);
                }
            }
        }
        float4 acc = make_float4(acc0.x + acc1.x, acc0.y + acc1.y,
                                 acc0.z + acc1.z, acc0.w + acc1.w);
        size_t o = ((size_t)bp * Nn + j) * Nn + (size_t)ks * Gc + gb * 32 + gq * 4;
        *(float4*)(g_zf + o) = acc;
        __nv_bfloat16 h0, l0, h1, l1, h2, l2, h3, l3;
        split2(acc.x, h0, l0);
        split2(acc.y, h1, l1);
        split2(acc.z, h2, l2);
        split2(acc.w, h3, l3);
        __nv_bfloat162 ph01, ph23, pl01, pl23;
        ph01.x = h0; ph01.y = h1; ph23.x = h2; ph23.y = h3;
        pl01.x = l0; pl01.y = l1; pl23.x = l2; pl23.y = l3;
        *(__nv_bfloat162*)(g_zh + o) = ph01;
        *(__nv_bfloat162*)(g_zh + o + 2) = ph23;
        *(__nv_bfloat162*)(g_zl + o) = pl01;
        *(__nv_bfloat162*)(g_zl + o + 2) = pl23;
    }
}

// ======================= 7. HMMA filter GEMM ===================================
#define TBK 32
#define NCH (Nn / TBK)
#define ASTG 16384
#define BSTG 16384
#define STG (ASTG + BSTG)
#define NSTAGE 3
#define SMEM_GEMM (NSTAGE * STG)

__global__ void __launch_bounds__(256, 2)
mma_gemm(const float* __restrict__ bias, float* __restrict__ out) {
    extern __shared__ __align__(1024) char smem[];
    uint32_t sb = smem_u32(smem);
    const int bp = blockIdx.z, p = bp & 3;
    const int m0 = blockIdx.y * 128, n0 = blockIdx.x * 128;
    const int tid = threadIdx.x, wid = tid >> 5, lane = tid & 31;
    const int warp_m = wid >> 2, warp_n = wid & 3;
    const size_t NN = (size_t)Nn * Nn;

    const __nv_bfloat16* Ah = g_fwh + (size_t)p * Fc * Nn;
    const __nv_bfloat16* Al = g_fwl + (size_t)p * Fc * Nn;
    const __nv_bfloat16* Bh = g_zh + (size_t)bp * NN;
    const __nv_bfloat16* Bl = g_zl + (size_t)bp * NN;

    float acc[4][4][4];
#pragma unroll
    for (int i = 0; i < 4; ++i)
#pragma unroll
        for (int j = 0; j < 4; ++j)
#pragma unroll
            for (int q = 0; q < 4; ++q) acc[i][j][q] = 0.f;

    auto load_stage = [&](int c, int s) {
        uint32_t base = sb + s * STG;
        int k0 = c * TBK;
#pragma unroll
        for (int i = 0; i < 4; ++i) {
            int idx = i * 256 + tid;
            int r = idx >> 3, ch = idx & 7;
            const __nv_bfloat16* srcp = ((ch < 4) ? Ah : Al) + (size_t)(m0 + r) * Nn + k0 + (ch & 3) * 8;
            cpa16(base + SWZ(r * 128 + ch * 16), srcp);
        }
#pragma unroll
        for (int i = 0; i < 4; ++i) {
            int idx = i * 256 + tid;
            int r = idx >> 3, ch = idx & 7;
            const __nv_bfloat16* srcp = ((ch < 4) ? Bh : Bl) + (size_t)(n0 + r) * Nn + k0 + (ch & 3) * 8;
            cpa16(base + ASTG + SWZ(r * 128 + ch * 16), srcp);
        }
        cpa_commit();
    };

    const int a_row = (lane & 7) + ((lane >> 3) & 1) * 8;
    const int a_k16 = lane >> 4;
    const int b_row = (lane & 7);
    const int b_par = (lane >> 3) & 1;

    load_stage(0, 0);
    load_stage(1, 1);
    for (int c = 0; c < NCH; ++c) {
        if (c + 2 < NCH) {
            load_stage(c + 2, (c + 2) % NSTAGE);
            cpa_wait2();
        } else if (c + 1 < NCH) {
            cpa_wait1();
        } else {
            cpa_wait0();
        }
        __syncthreads();
        uint32_t Abase = sb + (c % NSTAGE) * STG;
        uint32_t Bbase = Abase + ASTG;
#pragma unroll
        for (int s = 0; s < 2; ++s) {
            uint32_t bh2[4][2], bl2[4][2];
#pragma unroll
            for (int o = 0; o < 4; ++o) {
                int row = warp_n * 32 + o * 8 + b_row;
                int chk = s * 2 + b_par;
                ldm_x2(bh2[o][0], bh2[o][1], Bbase + SWZ(row * 128 + chk * 16));
                ldm_x2(bl2[o][0], bl2[o][1], Bbase + SWZ(row * 128 + 64 + chk * 16));
            }
            uint32_t ah[4][4], al[4][4];
#pragma unroll
            for (int mt = 0; mt < 4; ++mt) {
                int row = warp_m * 64 + mt * 16 + a_row;
                int chh = s * 2 + a_k16;
                ldm_x4(ah[mt][0], ah[mt][1], ah[mt][2], ah[mt][3],
                       Abase + SWZ(row * 128 + chh * 16));
                ldm_x4(al[mt][0], al[mt][1], al[mt][2], al[mt][3],
                       Abase + SWZ(row * 128 + 64 + chh * 16));
            }
#pragma unroll
            for (int mt = 0; mt < 4; ++mt)
#pragma unroll
                for (int o = 0; o < 4; ++o) mma16816(acc[mt][o], ah[mt], bh2[o]);
#pragma unroll
            for (int mt = 0; mt < 4; ++mt)
#pragma unroll
                for (int o = 0; o < 4; ++o) mma16816(acc[mt][o], ah[mt], bl2[o]);
#pragma unroll
            for (int mt = 0; mt < 4; ++mt)
#pragma unroll
                for (int o = 0; o < 4; ++o) mma16816(acc[mt][o], al[mt], bh2[o]);
        }
        __syncthreads();
    }

    float* C = out + (size_t)bp * Fc * Nn;
    const int r_base = m0 + warp_m * 64 + (lane >> 2);
    const int c_base = n0 + warp_n * 32 + (lane & 3) * 2;
#pragma unroll
    for (int mt = 0; mt < 4; ++mt)
#pragma unroll
        for (int o = 0; o < 4; ++o) {
#pragma unroll
            for (int h = 0; h < 2; ++h) {
                int r = r_base + mt * 16 + h * 8;
                int cc = c_base + o * 8;
                float bv = bias[r];
                float t0 = acc[mt][o][2 * h] + bv;
                float t1 = acc[mt][o][2 * h + 1] + bv;
                t0 = t0 > 0.f ? t0 : 0.01f * t0;
                t1 = t1 > 0.f ? t1 : 0.01f * t1;
                *(float2*)(C + (size_t)r * Nn + cc) = make_float2(t0, t1);
            }
        }
}

// ======================= launch ================================================
extern "C" void kernel_launch(void* const* d_in, const int* in_sizes, int n_in,
                              void* d_out, int out_size) {
    const float* x      = (const float*)d_in[0];
    const float* mixer  = (const float*)d_in[1];
    const float* weight = (const float*)d_in[2];
    const float* wb     = (const float*)d_in[3];
    const float* fw     = (const float*)d_in[4];
    const float* bias   = (const float*)d_in[5];
    const float* S      = (const float*)d_in[6];
    float* out = (float*)d_out;

    cudaFuncSetAttribute(mma_gemm, cudaFuncAttributeMaxDynamicSharedMemorySize, SMEM_GEMM);
    cudaFuncSetAttribute(prop_kernel, cudaFuncAttributeMaxDynamicSharedMemorySize, 131072);

    idx_kernel<<<dim3(Nn / 8, Bc), 256>>>(S);                            // 1
    pe_kernel<<<dim3(Nn / 256, NBP), 256>>>(x, mixer, weight, wb);       // 2
    ms_kernel<<<dim3(Nn, NBP), 256>>>(S);                                // 3
    fill_kernel<<<dim3(Nn / 8, NBP), 256>>>();                           // 4
    split_kernel<<<dim3(Nn / 32, Gc / 32, Bc), dim3(32, 8)>>>(x, fw);    // 5

    for (int k = 1; k < Kc; ++k)                                         // 6,7,8
        prop_kernel<<<dim3(8, NBP), 256, 131072>>>(k);

    mma_gemm<<<dim3(Nn / 128, Fc / 128, NBP), 256, SMEM_GEMM>>>(bias, out);  // 9
}

// round 11
// speedup vs baseline: 2.5362x; 1.3256x over previous
#include <cuda_runtime.h>
#include <cuda_bf16.h>
#include <cstdint>

#define Bc 8
#define Gc 256
#define Nn 1024
#define Pc 4
#define Fc 256
#define Kc 4
#define NBP 32
#define MAXS 128

// ======================= device scratch ======================================
__device__ float g_e1[NBP * Nn];
__device__ float g_e2[NBP * Nn];
__device__ float g_m[NBP * Nn];
__device__ float g_s[NBP * Nn];
__device__ int g_cnt[Bc * Nn];
__device__ unsigned short g_idx[(size_t)Bc * Nn * MAXS];    // 2 MB
__device__ float2 g_avi[(size_t)NBP * Nn * MAXS];           // 32 MB (value, i-bits), zero-padded
__device__ float g_zf[(size_t)NBP * Nn * Nn];               // 128 MB zT fp32 [bp][n][kG]
__device__ __nv_bfloat16 g_zh[(size_t)NBP * Nn * Nn];       // 64 MB zT hi
__device__ __nv_bfloat16 g_zl[(size_t)NBP * Nn * Nn];       // 64 MB zT lo
__device__ __nv_bfloat16 g_fwh[(size_t)Pc * Fc * Kc * Gc];
__device__ __nv_bfloat16 g_fwl[(size_t)Pc * Fc * Kc * Gc];

__device__ __forceinline__ void split2(float v, __nv_bfloat16& h, __nv_bfloat16& l) {
    h = __float2bfloat16(v);
    l = __float2bfloat16(v - __bfloat162float(h));
}

// ======================= helpers =============================================
__device__ __forceinline__ uint32_t smem_u32(const void* p) {
    uint32_t a;
    asm("{ .reg .u64 t; cvta.to.shared.u64 t, %1; cvt.u32.u64 %0, t; }" : "=r"(a) : "l"(p));
    return a;
}
__device__ __forceinline__ void cpa16(uint32_t dst, const void* src) {
    asm volatile("cp.async.cg.shared.global [%0], [%1], 16;" :: "r"(dst), "l"(src));
}
__device__ __forceinline__ void cpa_commit() { asm volatile("cp.async.commit_group;" ::: "memory"); }
__device__ __forceinline__ void cpa_wait2() { asm volatile("cp.async.wait_group 2;" ::: "memory"); }
__device__ __forceinline__ void cpa_wait1() { asm volatile("cp.async.wait_group 1;" ::: "memory"); }
__device__ __forceinline__ void cpa_wait0() { asm volatile("cp.async.wait_group 0;" ::: "memory"); }

#define SWZ(off) ((off) ^ (((off) >> 3) & 0x70))

__device__ __forceinline__ void ldm_x4(uint32_t& r0, uint32_t& r1, uint32_t& r2, uint32_t& r3,
                                       uint32_t addr) {
    asm volatile("ldmatrix.sync.aligned.m8n8.x4.shared.b16 {%0,%1,%2,%3}, [%4];"
                 : "=r"(r0), "=r"(r1), "=r"(r2), "=r"(r3) : "r"(addr));
}
__device__ __forceinline__ void ldm_x2(uint32_t& r0, uint32_t& r1, uint32_t addr) {
    asm volatile("ldmatrix.sync.aligned.m8n8.x2.shared.b16 {%0,%1}, [%2];"
                 : "=r"(r0), "=r"(r1) : "r"(addr));
}
__device__ __forceinline__ void mma16816(float* c, const uint32_t* a, const uint32_t* b) {
    asm volatile(
        "mma.sync.aligned.m16n8k16.row.col.f32.bf16.bf16.f32 "
        "{%0,%1,%2,%3}, {%4,%5,%6,%7}, {%8,%9}, {%0,%1,%2,%3};"
        : "+f"(c[0]), "+f"(c[1]), "+f"(c[2]), "+f"(c[3])
        : "r"(a[0]), "r"(a[1]), "r"(a[2]), "r"(a[3]), "r"(b[0]), "r"(b[1]));
}

// ======================= reductions ==========================================
__device__ __forceinline__ float blockReduceMax(float v, float* sm) {
#pragma unroll
    for (int o = 16; o; o >>= 1) v = fmaxf(v, __shfl_xor_sync(0xffffffffu, v, o));
    if ((threadIdx.x & 31) == 0) sm[threadIdx.x >> 5] = v;
    __syncthreads();
    if (threadIdx.x < 32) {
        float t = (threadIdx.x < 8) ? sm[threadIdx.x] : -3.0e38f;
#pragma unroll
        for (int o = 4; o; o >>= 1) t = fmaxf(t, __shfl_xor_sync(0xffffffffu, t, o));
        if (threadIdx.x == 0) sm[0] = t;
    }
    __syncthreads();
    float r = sm[0];
    __syncthreads();
    return r;
}
__device__ __forceinline__ float blockReduceSum(float v, float* sm) {
#pragma unroll
    for (int o = 16; o; o >>= 1) v += __shfl_xor_sync(0xffffffffu, v, o);
    if ((threadIdx.x & 31) == 0) sm[threadIdx.x >> 5] = v;
    __syncthreads();
    if (threadIdx.x < 32) {
        float t = (threadIdx.x < 8) ? sm[threadIdx.x] : 0.f;
#pragma unroll
        for (int o = 4; o; o >>= 1) t += __shfl_xor_sync(0xffffffffu, t, o);
        if (threadIdx.x == 0) sm[0] = t;
    }
    __syncthreads();
    float r = sm[0];
    __syncthreads();
    return r;
}

// ======================= 1. fused pe + idx =====================================
// bid < 128: pe block (bp = bid>>2, n-block = bid&3)
// else: idx block (fb = bid-128, b = fb>>7, j = (fb&127)*8 + warp)
__global__ void peidx_kernel(const float* __restrict__ x,
                             const float* __restrict__ mixer,
                             const float* __restrict__ weight,
                             const float* __restrict__ wb,
                             const float* __restrict__ S) {
    __shared__ __align__(16) char sbuf[16896];
    int bid = blockIdx.x, tid = threadIdx.x;
    if (bid < 128) {
        int bp = bid >> 2;
        int b = bp >> 2, p = bp & 3;
        float* s1 = (float*)sbuf;
        float* s2 = s1 + Gc;
        float* sc = s2 + Gc;
        {
            int g = tid;
            float v1 = 0.f, v2 = 0.f;
            const float* mw1 = mixer + p * 2 * Fc;
            const float* mw2 = mw1 + Fc;
#pragma unroll 8
            for (int f = 0; f < Fc; ++f) {
                float w = weight[((size_t)(p * Fc + f)) * Gc + g];
                v1 = fmaf(mw1[f], w, v1);
                v2 = fmaf(mw2[f], w, v2);
            }
            s1[g] = v1;
            s2[g] = v2;
            if (g == 0) {
                float c1 = 0.f, c2 = 0.f;
                for (int f = 0; f < Fc; ++f) {
                    c1 = fmaf(mw1[f], wb[p * Fc + f], c1);
                    c2 = fmaf(mw2[f], wb[p * Fc + f], c2);
                }
                sc[0] = c1;
                sc[1] = c2;
            }
        }
        __syncthreads();
        int n = (bid & 3) * 256 + tid;
        const float* xb = x + (size_t)b * Gc * Nn + n;
        float a1 = 0.f, a2 = 0.f;
#pragma unroll 8
        for (int g = 0; g < Gc; ++g) {
            float xv = xb[(size_t)g * Nn];
            a1 = fmaf(s1[g], xv, a1);
            a2 = fmaf(s2[g], xv, a2);
        }
        g_e1[bp * Nn + n] = a1 + sc[0];
        g_e2[bp * Nn + n] = a2 + sc[1];
    } else {
        int fb = bid - 128;
        int b = fb >> 7;
        int w = tid >> 5, lane = tid & 31;
        int j = (fb & 127) * 8 + w;
        unsigned short(*tmp)[1024] = (unsigned short(*)[1024])sbuf;
        const float* Sb = S + (size_t)b * Nn * Nn + j;
        int r0 = lane * 32;
        int c = 0;
#pragma unroll 4
        for (int r = 0; r < 32; ++r) {
            float s = __ldg(Sb + (size_t)(r0 + r) * Nn);
            if (fabsf(s) > 1e-9f) tmp[w][r0 + c++] = (unsigned short)(r0 + r);
        }
        int incl = c;
#pragma unroll
        for (int o = 1; o < 32; o <<= 1) {
            int t = __shfl_up_sync(0xffffffffu, incl, o);
            if (lane >= o) incl += t;
        }
        int excl = incl - c;
        int total = __shfl_sync(0xffffffffu, incl, 31);
        unsigned short* ipout = g_idx + ((size_t)b * Nn + j) * MAXS;
        for (int t = 0; t < c; ++t) {
            int pos = excl + t;
            if (pos < MAXS) ipout[pos] = tmp[w][r0 + t];
        }
        if (lane == 0) g_cnt[b * Nn + j] = total < MAXS ? total : MAXS;
    }
}

// ======================= 2. ms: per-row softmax stats ==========================
__global__ void ms_kernel(const float* __restrict__ S) {
    int i = blockIdx.x, bp = blockIdx.y, b = bp >> 2;
    __shared__ float sm[8];
    float e2i = g_e2[bp * Nn + i];
    const float* e1r = g_e1 + bp * Nn;
    const float* Sr = S + (size_t)b * Nn * Nn + (size_t)i * Nn;
    float lv[4];
    int mk[4];
    float vmax = -3.0e38f;
#pragma unroll
    for (int q = 0; q < 4; ++q) {
        int j = threadIdx.x + q * 256;
        float s = Sr[j];
        int m = (fabsf(s) > 1e-9f);
        float e = e1r[j] + e2i;
        float l = e > 0.f ? e : 0.2f * e;
        lv[q] = l;
        mk[q] = m;
        if (m) vmax = fmaxf(vmax, l);
    }
    vmax = blockReduceMax(vmax, sm);
    float sum = 0.f;
#pragma unroll
    for (int q = 0; q < 4; ++q)
        sum += mk[q] ? __expf(lv[q] - vmax) : 0.f;
    sum = blockReduceSum(sum, sm);
    if (threadIdx.x == 0) {
        g_m[bp * Nn + i] = vmax;
        g_s[bp * Nn + i] = sum;
    }
}

// ======================= 3. fused fill + split =================================
// bid < 4096: fill (bp = bid>>7, j = (bid&127)*8 + warp), zero-pads full MAXS row
// else: split (sbid = bid-4096: n0 = (sbid&31)*32, g0 = ((sbid>>5)&7)*32, b = sbid>>8)
__global__ void fillsplit_kernel(const float* __restrict__ x, const float* __restrict__ fw) {
    __shared__ float t[32][33];
    int bid = blockIdx.x, tid = threadIdx.x;
    if (bid < 4096) {
        int bp = bid >> 7, b = bp >> 2;
        int w = tid >> 5, lane = tid & 31;
        int j = (bid & 127) * 8 + w;
        int cnt = g_cnt[b * Nn + j];
        float e1j = g_e1[bp * Nn + j];
        const unsigned short* ip = g_idx + ((size_t)b * Nn + j) * MAXS;
        float2* ap = g_avi + ((size_t)bp * Nn + j) * MAXS;
#pragma unroll
        for (int s = lane; s < MAXS; s += 32) {
            float2 o = make_float2(0.f, __int_as_float(0));
            if (s < cnt) {
                int i = ip[s];
                float e = e1j + g_e2[bp * Nn + i];
                float l = e > 0.f ? e : 0.2f * e;
                o = make_float2(__expf(l - g_m[bp * Nn + i]) / g_s[bp * Nn + i], __int_as_float(i));
            }
            ap[s] = o;
        }
    } else {
        int sbid = bid - 4096;
        int b = sbid >> 8;
        int g0 = ((sbid >> 5) & 7) * 32, n0 = (sbid & 31) * 32;
        int tx = tid & 31, ty = tid >> 5;
        const float* xp = x + ((size_t)b * Gc + g0) * Nn + n0;
#pragma unroll
        for (int q = 0; q < 4; ++q) {
            int g = ty + q * 8;
            t[g][tx] = xp[(size_t)g * Nn + tx];
        }
        __syncthreads();
#pragma unroll
        for (int q = 0; q < 4; ++q) {
            int nn = ty + q * 8;
            float v = t[tx][nn];
            __nv_bfloat16 h, l;
            split2(v, h, l);
#pragma unroll
            for (int p = 0; p < 4; ++p) {
                size_t o = (((size_t)(b * 4 + p) * Nn) + n0 + nn) * Nn + g0 + tx;
                g_zf[o] = v;
                g_zh[o] = h;
                g_zl[o] = l;
            }
        }
        const int FT = Pc * Fc * Kc * Gc;
        int tot = 2048 * 256;
        int gid = sbid * 256 + tid;
        for (int i = gid; i < FT; i += tot) {
            __nv_bfloat16 h, l;
            split2(fw[i], h, l);
            g_fwh[i] = h;
            g_fwl[i] = l;
        }
    }
}

// ======================= 4. prop v4: cp.async-staged sparse propagation =======
// CTA = (g-block 32, bp), 512 threads (16 warps), occ 1.
// smem: zin [1024 i][32 g] fp32 (128 KB) + per-warp double-buffered (a,i) stage
//       (2 x 4 j x 16 s x 8B, 144B j-stride for bank spread) = 18 KB.
// Warp handles 4 j per iteration; lane = (jj 0..3, gq 0..7).
// Inner: LDS.64 broadcast (staged a,i) + LDS.128 zin + 4 FMA. No gmem in loop.
#define PSTG_OFF (Nn * 32 * 4)         /* 131072 */
#define WSTG 1152
#define PSMEM (PSTG_OFF + 16 * WSTG)   /* 149504 */

__global__ void __launch_bounds__(512, 1)
prop_kernel(int ks) {
    extern __shared__ __align__(16) char psm[];
    float* zin = (float*)psm;
    const float2* stg = (const float2*)(psm + PSTG_OFF);
    uint32_t sb = smem_u32(psm);
    const int bp = blockIdx.y, b = bp >> 2, gb = blockIdx.x;
    const int tid = threadIdx.x, w = tid >> 5, lane = tid & 31;
    const int jj = lane >> 3, gq = lane & 7;
    const int soff = lane & 7;
    const size_t NN = (size_t)Nn * Nn;

    const float* src = g_zf + (size_t)bp * NN + (size_t)(ks - 1) * Gc + (size_t)gb * 32;
#pragma unroll
    for (int r = 0; r < 16; ++r) {
        int idx = r * 512 + tid;
        int row = idx >> 3, c4 = idx & 7;
        float4 v = *(const float4*)(src + (size_t)row * Nn + c4 * 4);
        *(float4*)(zin + row * 32 + c4 * 4) = v;
    }
    __syncthreads();

    const uint32_t stga = sb + PSTG_OFF + w * WSTG + jj * 144 + soff * 16;

    for (int jb = w * 4; jb < Nn; jb += 64) {
        int cj = g_cnt[b * Nn + jb + (lane & 3)];
        cj = max(cj, __shfl_xor_sync(0xffffffffu, cj, 1));
        cj = max(cj, __shfl_xor_sync(0xffffffffu, cj, 2));
        int nch = (cj + 15) >> 4;
        const float2* arow = g_avi + ((size_t)bp * Nn + jb + jj) * MAXS;

        cpa16(stga, arow + soff * 2);
        cpa_commit();
        float4 acc0 = make_float4(0.f, 0.f, 0.f, 0.f);
        float4 acc1 = make_float4(0.f, 0.f, 0.f, 0.f);
        for (int c = 0; c < nch; ++c) {
            if (c + 1 < nch) {
                cpa16(stga + ((c + 1) & 1) * 576, arow + (c + 1) * 16 + soff * 2);
                cpa_commit();
                cpa_wait1();
            } else {
                cpa_wait0();
            }
            __syncwarp();
            const float2* bufp = stg + (w * 144 + (c & 1) * 72 + jj * 18);
#pragma unroll
            for (int q = 0; q < 16; ++q) {
                float2 av = bufp[q];
                int i = __float_as_int(av.y);
                float a = av.x;
                const float4 zv = *(const float4*)(zin + i * 32 + gq * 4);
                if (q & 1) {
                    acc1.x = fmaf(a, zv.x, acc1.x);
                    acc1.y = fmaf(a, zv.y, acc1.y);
                    acc1.z = fmaf(a, zv.z, acc1.z);
                    acc1.w = fmaf(a, zv.w, acc1.w);
                } else {
                    acc0.x = fmaf(a, zv.x, acc0.x);
                    acc0.y = fmaf(a, zv.y, acc0.y);
                    acc0.z = fmaf(a, zv.z, acc0.z);
                    acc0.w = fmaf(a, zv.w, acc0.w);
                }
            }
            __syncwarp();
        }
        float4 acc = make_float4(acc0.x + acc1.x, acc0.y + acc1.y,
                                 acc0.z + acc1.z, acc0.w + acc1.w);
        int j = jb + jj;
        size_t o = ((size_t)bp * Nn + j) * Nn + (size_t)ks * Gc + gb * 32 + gq * 4;
        *(float4*)(g_zf + o) = acc;
        __nv_bfloat16 h0, l0, h1, l1, h2, l2, h3, l3;
        split2(acc.x, h0, l0);
        split2(acc.y, h1, l1);
        split2(acc.z, h2, l2);
        split2(acc.w, h3, l3);
        __nv_bfloat162 ph01, ph23, pl01, pl23;
        ph01.x = h0; ph01.y = h1; ph23.x = h2; ph23.y = h3;
        pl01.x = l0; pl01.y = l1; pl23.x = l2; pl23.y = l3;
        *(__nv_bfloat162*)(g_zh + o) = ph01;
        *(__nv_bfloat162*)(g_zh + o + 2) = ph23;
        *(__nv_bfloat162*)(g_zl + o) = pl01;
        *(__nv_bfloat162*)(g_zl + o + 2) = pl23;
    }
}

// ======================= 5. HMMA filter GEMM ===================================
#define TBK 32
#define NCH (Nn / TBK)
#define ASTG 16384
#define BSTG 16384
#define STG (ASTG + BSTG)
#define NSTAGE 3
#define SMEM_GEMM (NSTAGE * STG)

__global__ void __launch_bounds__(256, 2)
mma_gemm(const float* __restrict__ bias, float* __restrict__ out) {
    extern __shared__ __align__(1024) char smem[];
    uint32_t sb = smem_u32(smem);
    const int bp = blockIdx.z, p = bp & 3;
    const int m0 = blockIdx.y * 128, n0 = blockIdx.x * 128;
    const int tid = threadIdx.x, wid = tid >> 5, lane = tid & 31;
    const int warp_m = wid >> 2, warp_n = wid & 3;
    const size_t NN = (size_t)Nn * Nn;

    const __nv_bfloat16* Ah = g_fwh + (size_t)p * Fc * Nn;
    const __nv_bfloat16* Al = g_fwl + (size_t)p * Fc * Nn;
    const __nv_bfloat16* Bh = g_zh + (size_t)bp * NN;
    const __nv_bfloat16* Bl = g_zl + (size_t)bp * NN;

    float acc[4][4][4];
#pragma unroll
    for (int i = 0; i < 4; ++i)
#pragma unroll
        for (int j = 0; j < 4; ++j)
#pragma unroll
            for (int q = 0; q < 4; ++q) acc[i][j][q] = 0.f;

    auto load_stage = [&](int c, int s) {
        uint32_t base = sb + s * STG;
        int k0 = c * TBK;
#pragma unroll
        for (int i = 0; i < 4; ++i) {
            int idx = i * 256 + tid;
            int r = idx >> 3, ch = idx & 7;
            const __nv_bfloat16* srcp = ((ch < 4) ? Ah : Al) + (size_t)(m0 + r) * Nn + k0 + (ch & 3) * 8;
            cpa16(base + SWZ(r * 128 + ch * 16), srcp);
        }
#pragma unroll
        for (int i = 0; i < 4; ++i) {
            int idx = i * 256 + tid;
            int r = idx >> 3, ch = idx & 7;
            const __nv_bfloat16* srcp = ((ch < 4) ? Bh : Bl) + (size_t)(n0 + r) * Nn + k0 + (ch & 3) * 8;
            cpa16(base + ASTG + SWZ(r * 128 + ch * 16), srcp);
        }
        cpa_commit();
    };

    const int a_row = (lane & 7) + ((lane >> 3) & 1) * 8;
    const int a_k16 = lane >> 4;
    const int b_row = (lane & 7);
    const int b_par = (lane >> 3) & 1;

    load_stage(0, 0);
    load_stage(1, 1);
    for (int c = 0; c < NCH; ++c) {
        if (c + 2 < NCH) {
            load_stage(c + 2, (c + 2) % NSTAGE);
            cpa_wait2();
        } else if (c + 1 < NCH) {
            cpa_wait1();
        } else {
            cpa_wait0();
        }
        __syncthreads();
        uint32_t Abase = sb + (c % NSTAGE) * STG;
        uint32_t Bbase = Abase + ASTG;
#pragma unroll
        for (int s = 0; s < 2; ++s) {
            uint32_t bh2[4][2], bl2[4][2];
#pragma unroll
            for (int o = 0; o < 4; ++o) {
                int row = warp_n * 32 + o * 8 + b_row;
                int chk = s * 2 + b_par;
                ldm_x2(bh2[o][0], bh2[o][1], Bbase + SWZ(row * 128 + chk * 16));
                ldm_x2(bl2[o][0], bl2[o][1], Bbase + SWZ(row * 128 + 64 + chk * 16));
            }
            uint32_t ah[4][4], al[4][4];
#pragma unroll
            for (int mt = 0; mt < 4; ++mt) {
                int row = warp_m * 64 + mt * 16 + a_row;
                int chh = s * 2 + a_k16;
                ldm_x4(ah[mt][0], ah[mt][1], ah[mt][2], ah[mt][3],
                       Abase + SWZ(row * 128 + chh * 16));
                ldm_x4(al[mt][0], al[mt][1], al[mt][2], al[mt][3],
                       Abase + SWZ(row * 128 + 64 + chh * 16));
            }
#pragma unroll
            for (int mt = 0; mt < 4; ++mt)
#pragma unroll
                for (int o = 0; o < 4; ++o) mma16816(acc[mt][o], ah[mt], bh2[o]);
#pragma unroll
            for (int mt = 0; mt < 4; ++mt)
#pragma unroll
                for (int o = 0; o < 4; ++o) mma16816(acc[mt][o], ah[mt], bl2[o]);
#pragma unroll
            for (int mt = 0; mt < 4; ++mt)
#pragma unroll
                for (int o = 0; o < 4; ++o) mma16816(acc[mt][o], al[mt], bh2[o]);
        }
        __syncthreads();
    }

    float* C = out + (size_t)bp * Fc * Nn;
    const int r_base = m0 + warp_m * 64 + (lane >> 2);
    const int c_base = n0 + warp_n * 32 + (lane & 3) * 2;
#pragma unroll
    for (int mt = 0; mt < 4; ++mt)
#pragma unroll
        for (int o = 0; o < 4; ++o) {
#pragma unroll
            for (int h = 0; h < 2; ++h) {
                int r = r_base + mt * 16 + h * 8;
                int cc = c_base + o * 8;
                float bv = bias[r];
                float t0 = acc[mt][o][2 * h] + bv;
                float t1 = acc[mt][o][2 * h + 1] + bv;
                t0 = t0 > 0.f ? t0 : 0.01f * t0;
                t1 = t1 > 0.f ? t1 : 0.01f * t1;
                *(float2*)(C + (size_t)r * Nn + cc) = make_float2(t0, t1);
            }
        }
}

// ======================= launch ================================================
extern "C" void kernel_launch(void* const* d_in, const int* in_sizes, int n_in,
                              void* d_out, int out_size) {
    const float* x      = (const float*)d_in[0];
    const float* mixer  = (const float*)d_in[1];
    const float* weight = (const float*)d_in[2];
    const float* wb     = (const float*)d_in[3];
    const float* fw     = (const float*)d_in[4];
    const float* bias   = (const float*)d_in[5];
    const float* S      = (const float*)d_in[6];
    float* out = (float*)d_out;

    cudaFuncSetAttribute(mma_gemm, cudaFuncAttributeMaxDynamicSharedMemorySize, SMEM_GEMM);
    cudaFuncSetAttribute(prop_kernel, cudaFuncAttributeMaxDynamicSharedMemorySize, PSMEM);

    peidx_kernel<<<1152, 256>>>(x, mixer, weight, wb, S);      // 1
    ms_kernel<<<dim3(Nn, NBP), 256>>>(S);                      // 2
    fillsplit_kernel<<<6144, 256>>>(x, fw);                    // 3
    for (int k = 1; k < Kc; ++k)                               // 4 (profiled), 5, 6
        prop_kernel<<<dim3(8, NBP), 512, PSMEM>>>(k);
    mma_gemm<<<dim3(Nn / 128, Fc / 128, NBP), 256, SMEM_GEMM>>>(bias, out);  // 7
}